// round 8
// baseline (speedup 1.0000x reference)
#include <cuda_runtime.h>
#include <cuda_fp16.h>
#include <cstdint>
#include <cstddef>

typedef unsigned long long ull;

#define B_   8
#define EH_  768
#define T_   512
#define PH_  320
#define U_   128
#define JH_  320
#define C_   34
#define NPAD 40
#define NT5  5

// ---------------- scratch: e/p activations stored as half2 words ----------
__device__ __align__(16) uint32_t g_e[B_ * T_ * JH_ / 2];
__device__ __align__(16) uint32_t g_p[B_ * U_ * JH_ / 2];

// ---------------- helpers ----------------
__device__ __forceinline__ uint32_t f2tf32(float x) {
    uint32_t u;
    asm("cvt.rna.tf32.f32 %0, %1;" : "=r"(u) : "f"(x));
    return u;
}
__device__ __forceinline__ uint32_t pkh(float lo, float hi) {
    uint32_t d;
    asm("cvt.rn.f16x2.f32 %0, %1, %2;" : "=r"(d) : "f"(hi), "f"(lo));
    return d;
}
__device__ __forceinline__ uint32_t hadd2u(uint32_t a, uint32_t b) {
    uint32_t d;
    asm("add.f16x2 %0, %1, %2;" : "=r"(d) : "r"(a), "r"(b));
    return d;
}
__device__ __forceinline__ uint32_t hrelu2(uint32_t a) {
    uint32_t d;
    asm("max.f16x2 %0, %1, %2;" : "=r"(d) : "r"(a), "r"(0u));
    return d;
}
__device__ __forceinline__ void mma_tf32(float* d, const uint32_t* a,
                                         uint32_t b0, uint32_t b1) {
    asm volatile(
        "mma.sync.aligned.m16n8k8.row.col.f32.tf32.tf32.f32 "
        "{%0,%1,%2,%3}, {%4,%5,%6,%7}, {%8,%9}, {%0,%1,%2,%3};"
        : "+f"(d[0]), "+f"(d[1]), "+f"(d[2]), "+f"(d[3])
        : "r"(a[0]), "r"(a[1]), "r"(a[2]), "r"(a[3]), "r"(b0), "r"(b1));
}
__device__ __forceinline__ void mma_f16(float* d, const uint32_t* a,
                                        uint32_t b0, uint32_t b1) {
    asm volatile(
        "mma.sync.aligned.m16n8k16.row.col.f32.f16.f16.f32 "
        "{%0,%1,%2,%3}, {%4,%5,%6,%7}, {%8,%9}, {%0,%1,%2,%3};"
        : "+f"(d[0]), "+f"(d[1]), "+f"(d[2]), "+f"(d[3])
        : "r"(a[0]), "r"(a[1]), "r"(a[2]), "r"(a[3]), "r"(b0), "r"(b1));
}

// =====================================================================
// proj_kernel (unchanged from R6): tf32 MMA computing D^T = W @ X.
// Output packed half2 into g_e / g_p.
// =====================================================================
#define XS_STR 68
#define WS_STR 36
#define SS_STRW 36

__global__ void __launch_bounds__(128, 5) proj_kernel(
    const float* __restrict__ enc, const float* __restrict__ W_enc,
    const float* __restrict__ b_enc, const float* __restrict__ dec,
    const float* __restrict__ W_pred, const float* __restrict__ b_pred)
{
    __shared__ __align__(16) uint32_t sW[64 * WS_STR];
    __shared__ __align__(16) uint32_t sXS[64 * SS_STRW];

    const int blk = blockIdx.x;
    const float *X, *W, *bias;
    uint32_t* outw;
    int H, L, b, j0, l0;
    if (blk < 320) {
        b = blk / 40; int r = blk - b * 40;
        j0 = (r >> 3) * 64; l0 = (r & 7) * 64;
        X = enc; W = W_enc; bias = b_enc; outw = g_e; H = EH_; L = T_;
    } else {
        int bi = blk - 320; b = bi / 10; int r = bi - b * 10;
        j0 = (r >> 1) * 64; l0 = (r & 1) * 64;
        X = dec; W = W_pred; bias = b_pred; outw = g_p; H = PH_; L = U_;
    }
    const float* Xb = X + (size_t)b * H * L + l0;
    const float* Wb = W + (size_t)j0 * H;

    const int tid  = threadIdx.x;
    const int wid  = tid >> 5;
    const int lane = tid & 31;
    const int c    = lane & 3;
    const int rn   = lane >> 2;
    const int mpair = wid >> 1;
    const int nhalf = wid & 1;

    float acc[2][4][4];
    #pragma unroll
    for (int mt = 0; mt < 2; mt++)
        #pragma unroll
        for (int nt = 0; nt < 4; nt++)
            #pragma unroll
            for (int i = 0; i < 4; i++) acc[mt][nt][i] = 0.f;

    const uint32_t* aR0 = sW + (32 * mpair + rn) * WS_STR + c;
    const uint32_t* bR  = sXS + c * XS_STR + 32 * nhalf + rn;

    const int nk = H >> 5;
    for (int kc = 0; kc < nk; kc++) {
        const int k0 = kc * 32;
        #pragma unroll
        for (int i = 0; i < 4; i++) {
            int idx = tid + i * 128;
            int hh = idx >> 4, l4 = (idx & 15) * 4;
            float4 v = *(const float4*)(Xb + (size_t)(k0 + hh) * L + l4);
            uint4 u = make_uint4(f2tf32(v.x), f2tf32(v.y), f2tf32(v.z), f2tf32(v.w));
            *(uint4*)(sXS + hh * XS_STR + l4) = u;
        }
        #pragma unroll
        for (int i = 0; i < 4; i++) {
            int idx = tid + i * 128;
            int jj = idx >> 3, h4 = (idx & 7) * 4;
            float4 v = *(const float4*)(Wb + (size_t)jj * H + k0 + h4);
            uint4 u = make_uint4(f2tf32(v.x), f2tf32(v.y), f2tf32(v.z), f2tf32(v.w));
            *(uint4*)(sW + jj * WS_STR + h4) = u;
        }
        __syncthreads();
        #pragma unroll
        for (int k8 = 0; k8 < 4; k8++) {
            const int ko = k8 * 8;
            uint32_t a0[4], a1[4];
            const uint32_t* ar = aR0 + ko;
            a0[0] = ar[0];  a0[1] = ar[8 * WS_STR];
            a0[2] = ar[4];  a0[3] = ar[8 * WS_STR + 4];
            const uint32_t* ar1 = ar + 16 * WS_STR;
            a1[0] = ar1[0]; a1[1] = ar1[8 * WS_STR];
            a1[2] = ar1[4]; a1[3] = ar1[8 * WS_STR + 4];
            const uint32_t* br = bR + ko * XS_STR;
            #pragma unroll
            for (int nt = 0; nt < 4; nt++) {
                uint32_t b0 = br[8 * nt];
                uint32_t b1 = br[4 * XS_STR + 8 * nt];
                mma_tf32(acc[0][nt], a0, b0, b1);
                mma_tf32(acc[1][nt], a1, b0, b1);
            }
        }
        __syncthreads();
    }

    float bj[2][2];
    #pragma unroll
    for (int mt = 0; mt < 2; mt++) {
        int jr = j0 + 16 * (2 * mpair + mt) + rn;
        bj[mt][0] = bias[jr];
        bj[mt][1] = bias[jr + 8];
    }
    __half* sS = (__half*)sXS;
    #pragma unroll
    for (int mt = 0; mt < 2; mt++) {
        int jloc = 16 * (2 * mpair + mt) + rn;
        #pragma unroll
        for (int nt = 0; nt < 4; nt++) {
            int lloc = 8 * (4 * nhalf + nt) + 2 * c;
            sS[lloc * 72 + jloc]           = __float2half(acc[mt][nt][0] + bj[mt][0]);
            sS[(lloc + 1) * 72 + jloc]     = __float2half(acc[mt][nt][1] + bj[mt][0]);
            sS[lloc * 72 + jloc + 8]       = __float2half(acc[mt][nt][2] + bj[mt][1]);
            sS[(lloc + 1) * 72 + jloc + 8] = __float2half(acc[mt][nt][3] + bj[mt][1]);
        }
    }
    __syncthreads();
    #pragma unroll
    for (int i = 0; i < 4; i++) {
        int idx = tid + i * 128;
        int l = idx >> 3, q = idx & 7;
        uint4 v = *(const uint4*)(sXS + l * SS_STRW + q * 4);
        *(uint4*)(outw + ((size_t)b * L + l0 + l) * 160 + (j0 >> 1) + q * 4) = v;
    }
}

// =====================================================================
// joint_mma_kernel: fp16 mma.sync, pair-interleaved SMEM -> LDS.64 loads
//   Block 16u x 32t (2 x 16t tiles), 128 thr, warp = 4 m16(t) x 5 n8.
//   e/p rows: word w -> slot (w>>3)*8 + (w&3)*2 + ((w>>2)&1), stride 168.
//   W: [g][c][44 n][pair], pair = (w[k2+c], w[k2+c+4]).
//   4 blocks/SM (dynamic smem 49.8KB, regs capped 128).
// =====================================================================
#define EPS   168                       // e/p row stride (words)
#define WG44  44                        // padded n for W tiles
#define OFF_W 0
#define W_WORDS (20 * 4 * WG44 * 2)     // 7040
#define OFF_E (OFF_W + W_WORDS)         // 7040
#define E_WORDS (16 * EPS)              // 2688
#define OFF_P (OFF_E + E_WORDS)         // 9728
#define OFF_B (OFF_P + E_WORDS)         // 12416
#define SMEM_JT ((OFF_B + NPAD) * 4)    // 49824 B

__global__ void __launch_bounds__(128, 4) joint_mma_kernel(
    const float* __restrict__ W_out, const float* __restrict__ b_out,
    float* __restrict__ out)
{
    extern __shared__ __align__(16) uint32_t sm[];
    float* sB = (float*)(sm + OFF_B);

    const int tid  = threadIdx.x;
    const int wid  = tid >> 5;
    const int lane = tid & 31;
    const int c    = lane & 3;
    const int rn   = lane >> 2;
    const int c2   = c * 2;
    const int b    = blockIdx.y;
    const int u0   = blockIdx.x * 16;
    const int tz   = blockIdx.z;

    // ---- W_out -> [g][c][n][pair] half2 layout ----
    for (int idx = tid; idx < 160 * NPAD; idx += 128) {
        int n  = idx / 160;
        int k2 = idx - n * 160;
        uint32_t v = 0u;
        if (n < C_) {
            float2 w = *(const float2*)(W_out + (size_t)n * JH_ + 2 * k2);
            v = pkh(w.x, w.y);
        }
        int g = k2 >> 3, r = k2 & 7;
        sm[OFF_W + ((g * 4 + (r & 3)) * WG44 + n) * 2 + (r >> 2)] = v;
    }
    if (tid < NPAD) sB[tid] = (tid < C_) ? b_out[tid] : -1e30f;

    // ---- p tile (16 u rows), pair-interleaved ----
    {
        const uint4* src = (const uint4*)(g_p + ((size_t)b * U_ + u0) * 160);
        #pragma unroll
        for (int i = 0; i < 5; i++) {
            int idx = tid + i * 128;
            int row = idx / 40, q = idx - row * 40;
            uint4 v = src[idx];
            uint32_t* d = sm + OFF_P + row * EPS + (q >> 1) * 8 + (q & 1);
            d[0] = v.x; d[2] = v.y; d[4] = v.z; d[6] = v.w;
        }
    }

    const uint32_t* eB  = sm + OFF_E + (4 * wid) * EPS + c2;
    const uint32_t* pB0 = sm + OFF_P + rn * EPS + c2;
    const uint32_t* pB1 = pB0 + 8 * EPS;
    const uint32_t* wB  = sm + OFF_W + (c * WG44 + rn) * 2;
    float bn[NT5][2];

    for (int tt = 0; tt < 2; tt++) {
        const int t0 = tz * 32 + tt * 16;
        __syncthreads();
        // e tile, pair-interleaved
        {
            const uint4* src = (const uint4*)(g_e + ((size_t)b * T_ + t0) * 160);
            #pragma unroll
            for (int i = 0; i < 5; i++) {
                int idx = tid + i * 128;
                int row = idx / 40, q = idx - row * 40;
                uint4 v = src[idx];
                uint32_t* d = sm + OFF_E + row * EPS + (q >> 1) * 8 + (q & 1);
                d[0] = v.x; d[2] = v.y; d[4] = v.z; d[6] = v.w;
            }
        }
        __syncthreads();
        if (tt == 0) {
            #pragma unroll
            for (int nt = 0; nt < NT5; nt++) {
                bn[nt][0] = sB[nt * 8 + c2];
                bn[nt][1] = sB[nt * 8 + c2 + 1];
            }
        }

        float acc[4][NT5][4];
        #pragma unroll
        for (int mt = 0; mt < 4; mt++)
            #pragma unroll
            for (int nt = 0; nt < NT5; nt++)
                #pragma unroll
                for (int i = 0; i < 4; i++) acc[mt][nt][i] = 0.f;

        // ---- main loop: 20 k16 steps, all LDS.64 ----
        #pragma unroll 2
        for (int g = 0; g < 20; g++) {
            uint2 pv0 = *(const uint2*)(pB0 + 8 * g);
            uint2 pv1 = *(const uint2*)(pB1 + 8 * g);
            uint32_t A[4][4];
            #pragma unroll
            for (int mt = 0; mt < 4; mt++) {
                uint2 ev = *(const uint2*)(eB + mt * EPS + 8 * g);
                A[mt][0] = hrelu2(hadd2u(ev.x, pv0.x));
                A[mt][1] = hrelu2(hadd2u(ev.x, pv1.x));
                A[mt][2] = hrelu2(hadd2u(ev.y, pv0.y));
                A[mt][3] = hrelu2(hadd2u(ev.y, pv1.y));
            }
            #pragma unroll
            for (int nt = 0; nt < NT5; nt++) {
                uint2 wv = *(const uint2*)(wB + g * (4 * WG44 * 2) + nt * 16);
                #pragma unroll
                for (int mt = 0; mt < 4; mt++)
                    mma_f16(acc[mt][nt], A[mt], wv.x, wv.y);
            }
        }

        // ---- epilogue: bias + log_softmax, direct coalesced stores ----
        #pragma unroll
        for (int mt = 0; mt < 4; mt++) {
            const int t = t0 + 4 * wid + mt;
            #pragma unroll
            for (int hf = 0; hf < 2; hf++) {
                float v[NT5][2];
                #pragma unroll
                for (int nt = 0; nt < NT5; nt++) {
                    v[nt][0] = acc[mt][nt][hf * 2 + 0] + bn[nt][0];
                    v[nt][1] = acc[mt][nt][hf * 2 + 1] + bn[nt][1];
                }
                float m = v[0][0];
                #pragma unroll
                for (int nt = 0; nt < NT5; nt++) {
                    m = fmaxf(m, v[nt][0]);
                    m = fmaxf(m, v[nt][1]);
                }
                m = fmaxf(m, __shfl_xor_sync(0xffffffffu, m, 1));
                m = fmaxf(m, __shfl_xor_sync(0xffffffffu, m, 2));
                float s = 0.f;
                #pragma unroll
                for (int nt = 0; nt < NT5; nt++) {
                    s += __expf(v[nt][0] - m);
                    s += __expf(v[nt][1] - m);
                }
                s += __shfl_xor_sync(0xffffffffu, s, 1);
                s += __shfl_xor_sync(0xffffffffu, s, 2);
                float lse = m + __logf(s);

                const int u = u0 + rn + 8 * hf;
                float* o = out + (((size_t)b * T_ + t) * U_ + u) * C_;
                #pragma unroll
                for (int nt = 0; nt < 4; nt++)
                    *(float2*)(o + nt * 8 + c2) =
                        make_float2(v[nt][0] - lse, v[nt][1] - lse);
                if (c == 0)
                    *(float2*)(o + 32) = make_float2(v[4][0] - lse, v[4][1] - lse);
            }
        }
    }
}

// =====================================================================
// kernel_launch
// Inputs: enc, dec, W_enc, b_enc, W_pred, b_pred, W_out, b_out
// =====================================================================
extern "C" void kernel_launch(void* const* d_in, const int* in_sizes, int n_in,
                              void* d_out, int out_size)
{
    const float* enc    = (const float*)d_in[0];
    const float* dec    = (const float*)d_in[1];
    const float* W_enc  = (const float*)d_in[2];
    const float* b_enc  = (const float*)d_in[3];
    const float* W_pred = (const float*)d_in[4];
    const float* b_pred = (const float*)d_in[5];
    const float* W_out  = (const float*)d_in[6];
    const float* b_outp = (const float*)d_in[7];
    float* out = (float*)d_out;

    // dynamic smem opt-in (first call is the uncaptured correctness run)
    (void)cudaFuncSetAttribute(joint_mma_kernel,
                               cudaFuncAttributeMaxDynamicSharedMemorySize,
                               SMEM_JT);

    // proj: 320 enc + 80 dec blocks, single wave
    proj_kernel<<<400, 128>>>(enc, W_enc, b_enc, dec, W_pred, b_pred);

    // joint: x = u-tiles (8), y = batch (8), z = 32t groups (16)
    joint_mma_kernel<<<dim3(U_ / 16, B_, T_ / 32), 128, SMEM_JT>>>(
        W_out, b_outp, out);
}